// round 3
// baseline (speedup 1.0000x reference)
#include <cuda_runtime.h>

// ReceptiveFieldLayer: J=4, R=10, pad=3.
// out[b,c,i,j] = relu(max over 2-3 taps/axis of feat[b,x,y,c]), c in {0,1,2}
// Input : [16, 256, 256, 64] f32 NHWC.  Output: [16, 3, 1024, 1024] f32.
//
// Two-phase:
//  K1: compact channels 0..2 into planar scratch [16,3,256,256] (12.6 MB,
//      L2-resident) — isolates the scattered 256B-stride gather.
//  K2: tile kernel reads patch from scratch (L2 hits), writes the 201 MB
//      output as a near-pure sequential DRAM write stream (__stcs).

#define TILE_H 32
#define TILE_W 128
#define SH_H 10
#define SH_W 34
#define NPOS (SH_H * SH_W)   // 340

__device__ float g_scratch[16 * 3 * 256 * 256];   // [b][c][x][y]

__global__ __launch_bounds__(256)
void rf_compact_kernel(const float* __restrict__ in) {
    // one thread per feature position: reads float4 (ch 0..3), writes 3 planar floats
    const unsigned idx = blockIdx.x * 256u + threadIdx.x;     // b*65536 + x*256 + y
    const unsigned b   = idx >> 16;
    const unsigned xy  = idx & 0xFFFFu;
    const float4 v = __ldg(reinterpret_cast<const float4*>(in + ((size_t)idx << 6)));
    const unsigned base = (b * 3u) << 16;
    g_scratch[base + xy]            = v.x;
    g_scratch[base + (1u << 16) + xy] = v.y;
    g_scratch[base + (2u << 16) + xy] = v.z;
}

__global__ __launch_bounds__(256)
void rf_scatter_max_kernel(float* __restrict__ out) {
    __shared__ float sh[3][SH_H][SH_W];

    const int b  = blockIdx.z;
    const int i0 = blockIdx.y * TILE_H;
    const int j0 = blockIdx.x * TILE_W;
    const int fq = i0 >> 2;
    const int gq = j0 >> 2;
    const int tid = threadIdx.x;

    // ---- Load 3-channel patch from planar scratch (L2 hits), zero-padded ----
    for (int pos = tid; pos < NPOS; pos += 256) {
        int sx = pos / SH_W;
        int sy = pos - sx * SH_W;
        int fx = fq - 1 + sx;
        int fy = gq - 1 + sy;
        float x = 0.f, y = 0.f, z = 0.f;
        if ((unsigned)fx < 256u && (unsigned)fy < 256u) {
            unsigned off = ((unsigned)fx << 8) | (unsigned)fy;
            unsigned base = ((unsigned)b * 3u) << 16;
            x = g_scratch[base + off];
            y = g_scratch[base + (1u << 16) + off];
            z = g_scratch[base + (2u << 16) + off];
        }
        sh[0][sx][sy] = x;
        sh[1][sx][sy] = y;
        sh[2][sx][sy] = z;
    }
    __syncthreads();

    // ---- Each thread: 4x4 output block from a 3x3 shared patch ----
    const int q  = tid & 31;   // col group
    const int rg = tid >> 5;   // row group

    #pragma unroll
    for (int ch = 0; ch < 3; ch++) {
        float a00 = sh[ch][rg    ][q], a01 = sh[ch][rg    ][q + 1], a02 = sh[ch][rg    ][q + 2];
        float a10 = sh[ch][rg + 1][q], a11 = sh[ch][rg + 1][q + 1], a12 = sh[ch][rg + 1][q + 2];
        float a20 = sh[ch][rg + 2][q], a21 = sh[ch][rg + 2][q + 1], a22 = sh[ch][rg + 2][q + 2];

        float c0a = fmaxf(a00, a01), c0b = fmaxf(a01, a02), c0c = fmaxf(c0a, a02);
        float c1a = fmaxf(a10, a11), c1b = fmaxf(a11, a12), c1c = fmaxf(c1a, a12);
        float c2a = fmaxf(a20, a21), c2b = fmaxf(a21, a22), c2c = fmaxf(c2a, a22);

        float r01_a  = fmaxf(fmaxf(c0a, c1a), 0.f);
        float r01_c  = fmaxf(fmaxf(c0c, c1c), 0.f);
        float r01_b  = fmaxf(fmaxf(c0b, c1b), 0.f);
        float r012_a = fmaxf(r01_a, c2a);
        float r012_c = fmaxf(r01_c, c2c);
        float r012_b = fmaxf(r01_b, c2b);
        float r12_a  = fmaxf(fmaxf(c1a, c2a), 0.f);
        float r12_c  = fmaxf(fmaxf(c1c, c2c), 0.f);
        float r12_b  = fmaxf(fmaxf(c1b, c2b), 0.f);

        float4 v0 = make_float4(r01_a,  r01_c,  r01_c,  r01_b);
        float4 v1 = make_float4(r012_a, r012_c, r012_c, r012_b);
        float4 v3 = make_float4(r12_a,  r12_c,  r12_c,  r12_b);

        size_t base = ((((size_t)b * 3 + ch) * 1024) + (size_t)(i0 + rg * 4)) * 1024
                      + (size_t)(j0 + q * 4);
        float4* o = reinterpret_cast<float4*>(out + base);
        __stcs(o,        v0);
        __stcs(o +  256, v1);
        __stcs(o +  512, v1);
        __stcs(o +  768, v3);
    }
}

extern "C" void kernel_launch(void* const* d_in, const int* in_sizes, int n_in,
                              void* d_out, int out_size) {
    const float* in = (const float*)d_in[0];
    float* out = (float*)d_out;

    rf_compact_kernel<<<16 * 256 * 256 / 256, 256>>>(in);

    dim3 grid(1024 / TILE_W, 1024 / TILE_H, 16);   // (8, 32, 16)
    rf_scatter_max_kernel<<<grid, 256>>>(out);
}